// round 10
// baseline (speedup 1.0000x reference)
#include <cuda_runtime.h>
#include <cuda_fp16.h>
#include <math.h>
#include <cstdint>

// Problem constants
#define B_   8

// ---------------------------------------------------------------------------
// Global scratch (fp16, SW128-swizzled chunk blobs; blob layout == smem image)
// Q: per (b, qtile<32>): 4 chunks x 16KB ([128 rows][64 f], 128B rows, SW128)
// K: per (b, ktile<8>):  4 chunks x 16KB ([128 keys][64 f])
// V: per (b, ktile<8>):  2 chunks x 32KB ([256 f][64 keys]  (Vt))
// ---------------------------------------------------------------------------
__device__ uint4 g_Q4[(size_t)B_ * 32 * 4096];   // 16 MB
__device__ uint4 g_K4[(size_t)B_ * 8 * 4096];    //  4 MB
__device__ uint4 g_V4[(size_t)B_ * 8 * 4096];    //  4 MB

__device__ __forceinline__ uint32_t sw128(uint32_t o) { return o ^ ((o >> 3) & 0x70); }

__device__ __forceinline__ uint32_t smem_u32(const void* p) {
    uint32_t a;
    asm("{ .reg .u64 t; cvta.to.shared.u64 t, %1; cvt.u32.u64 %0, t; }" : "=r"(a) : "l"(p));
    return a;
}
__device__ __forceinline__ void ldsm4(uint32_t* r, uint32_t a) {
    asm volatile("ldmatrix.sync.aligned.m8n8.x4.shared.b16 {%0,%1,%2,%3}, [%4];"
                 : "=r"(r[0]), "=r"(r[1]), "=r"(r[2]), "=r"(r[3]) : "r"(a));
}
__device__ __forceinline__ void mma16816(float* d, const uint32_t* a, uint32_t b0, uint32_t b1) {
    asm volatile("mma.sync.aligned.m16n8k16.row.col.f32.f16.f16.f32 "
                 "{%0,%1,%2,%3}, {%4,%5,%6,%7}, {%8,%9}, {%0,%1,%2,%3};"
                 : "+f"(d[0]), "+f"(d[1]), "+f"(d[2]), "+f"(d[3])
                 : "r"(a[0]), "r"(a[1]), "r"(a[2]), "r"(a[3]), "r"(b0), "r"(b1));
}
__device__ __forceinline__ void sts128(uint32_t a, uint4 v) {
    asm volatile("st.shared.v4.b32 [%0], {%1,%2,%3,%4};"
                 :: "r"(a), "r"(v.x), "r"(v.y), "r"(v.z), "r"(v.w) : "memory");
}
__device__ __forceinline__ void sts32(uint32_t a, uint32_t v) {
    asm volatile("st.shared.b32 [%0], %1;" :: "r"(a), "r"(v) : "memory");
}

// ---------------------------------------------------------------------------
// Kernel 1: Q projection + L2 norm -> swizzled fp16 chunk blobs.
// Block: 256 thr = 8 warps (warp = n, lane = hw within 32-row strip).
// ---------------------------------------------------------------------------
__global__ void __launch_bounds__(256) qproj_kernel(const float* __restrict__ x,
                                                    const float* __restrict__ wq)
{
    __shared__ float s_w[64 * 32];        // [c][d]
    __shared__ float s_ss[8][32];
    __shared__ uint4 s_q[32 * 32];        // 32 rows x 32 16B-chunks (xor-swizzled)
    const int t = threadIdx.x;
    for (int i = t; i < 2048; i += 256) { int d = i >> 6, c = i & 63; s_w[c * 32 + d] = wq[i]; }
    __syncthreads();

    const int b = blockIdx.x >> 7, tile = blockIdx.x & 127;
    const int n = t >> 5, r = t & 31;
    const float* xp = x + (size_t)b * 64 * 8 * 4096 + (size_t)n * 4096 + tile * 32 + r;

    float acc[32];
#pragma unroll
    for (int d = 0; d < 32; d++) acc[d] = 0.f;
#pragma unroll 4
    for (int c = 0; c < 64; c++) {
        float xv = xp[(size_t)c * 32768];
#pragma unroll
        for (int m = 0; m < 8; m++) {
            float4 w4 = *(const float4*)&s_w[c * 32 + 4 * m];
            acc[4*m+0] += xv * w4.x; acc[4*m+1] += xv * w4.y;
            acc[4*m+2] += xv * w4.z; acc[4*m+3] += xv * w4.w;
        }
    }
    float ss = 0.f;
#pragma unroll
    for (int d = 0; d < 32; d++) ss += acc[d] * acc[d];
    s_ss[n][r] = ss;
    __syncthreads();
    float tot = 0.f;
#pragma unroll
    for (int w = 0; w < 8; w++) tot += s_ss[w][r];
    const float inv = 1.0f / fmaxf(sqrtf(tot), 1e-12f);

    __half* sq = (__half*)s_q;
#pragma unroll
    for (int d = 0; d < 32; d++)
        sq[r * 256 + ((d ^ r) << 3) + n] = __float2half_rn(acc[d] * inv);
    __syncthreads();

    const int qt = tile >> 2, rbase = (tile & 3) * 32;
    uint4* dst = g_Q4 + (size_t)(b * 32 + qt) * 4096;
    for (int i = t; i < 1024; i += 256) {
        int rr = i >> 5, j = i & 31;
        uint4 v = s_q[rr * 32 + (j ^ rr)];
        uint32_t off = sw128((uint32_t)(rbase + rr) * 128 + (j & 7) * 16);
        *(uint4*)((char*)(dst + (j >> 3) * 1024) + off) = v;
    }
}

// ---------------------------------------------------------------------------
// Kernel 2: KV projection (2x-subsampled grid) + K norm -> blobs.
// ---------------------------------------------------------------------------
__global__ void __launch_bounds__(256) kvproj_kernel(const float* __restrict__ x,
                                                     const float* __restrict__ wkv)
{
    __shared__ float s_w[64 * 64];        // [c][e]
    __shared__ float s_ss[8][32];
    __shared__ uint4 s_buf[1024];         // 16KB, reused K then V
    const int t = threadIdx.x;
    for (int i = t; i < 4096; i += 256) { int e = i >> 6, c = i & 63; s_w[c * 64 + e] = wkv[i]; }
    __syncthreads();

    const int b = blockIdx.x >> 5, h2 = blockIdx.x & 31;
    const int n = t >> 5, w2 = t & 31;
    const float* xp = x + (size_t)b * 64 * 8 * 4096 + (size_t)n * 4096 + (2 * h2) * 64 + 2 * w2;

    float acc[64];
#pragma unroll
    for (int e = 0; e < 64; e++) acc[e] = 0.f;
#pragma unroll 4
    for (int c = 0; c < 64; c++) {
        float xv = xp[(size_t)c * 32768];
#pragma unroll
        for (int m = 0; m < 16; m++) {
            float4 w4 = *(const float4*)&s_w[c * 64 + 4 * m];
            acc[4*m+0] += xv * w4.x; acc[4*m+1] += xv * w4.y;
            acc[4*m+2] += xv * w4.z; acc[4*m+3] += xv * w4.w;
        }
    }
    float ss = 0.f;
#pragma unroll
    for (int d = 0; d < 32; d++) ss += acc[d] * acc[d];
    s_ss[n][w2] = ss;
    __syncthreads();
    float tot = 0.f;
#pragma unroll
    for (int w = 0; w < 8; w++) tot += s_ss[w][w2];
    const float inv = 1.0f / fmaxf(sqrtf(tot), 1e-12f);

    // --- K stage + write ---
    __half* sk = (__half*)s_buf;
#pragma unroll
    for (int d = 0; d < 32; d++)
        sk[w2 * 256 + ((d ^ w2) << 3) + n] = __float2half_rn(acc[d] * inv);
    __syncthreads();
    const int kt = h2 >> 2, rbase = (h2 & 3) * 32;
    uint4* kd = g_K4 + (size_t)(b * 8 + kt) * 4096;
    for (int i = t; i < 1024; i += 256) {
        int rr = i >> 5, j = i & 31;
        uint4 v = s_buf[rr * 32 + (j ^ rr)];
        uint32_t off = sw128((uint32_t)(rbase + rr) * 128 + (j & 7) * 16);
        *(uint4*)((char*)(kd + (j >> 3) * 1024) + off) = v;
    }
    __syncthreads();

    // --- Vt stage ([f][32 keys]) + write ---
    __half* sv = (__half*)s_buf;
#pragma unroll
    for (int d = 0; d < 32; d++)
        sv[(d * 8 + n) * 32 + w2] = __float2half_rn(acc[32 + d]);
    __syncthreads();
    const int kc = (h2 & 3) >> 1, colbase = (h2 & 1) * 32;
    uint4* vd = g_V4 + ((size_t)(b * 8 + kt) * 2 + kc) * 2048;
    for (int i = t; i < 1024; i += 256) {
        int f = i >> 2, k8 = i & 3;
        uint4 v = s_buf[i];
        uint32_t off = sw128((uint32_t)f * 128 + colbase * 2 + k8 * 16);
        *(uint4*)((char*)vd + off) = v;
    }
}

// ---------------------------------------------------------------------------
// Kernel 3: HMMA (mma.sync m16n8k16) attention.
// Block = (b, 128-q tile), 256 thr = 8 warps in 4(M) x 2(N).
// Smem: Q 64K | K 64K | Vt 64K | P 32K | den 1K  (+align) = 226KB.
// ---------------------------------------------------------------------------
#define SDYN_BYTES (196608 + 32768 + 1024 + 1024)

__global__ void __launch_bounds__(256, 1) attn_kernel(float* __restrict__ out)
{
    extern __shared__ unsigned char smraw[];
    const uint32_t sbase = (smem_u32(smraw) + 1023) & ~1023u;
    const uint32_t QS = sbase, KS = sbase + 65536, VS = sbase + 131072;
    const uint32_t PS = sbase + 196608, DS = sbase + 229376;
    float* denp = (float*)(smraw + (size_t)(DS - smem_u32(smraw)));

    const int tid = threadIdx.x, lane = tid & 31, w = tid >> 5;
    const int wm = w & 3, wn = w >> 2;
    const int b = blockIdx.x >> 5, qt = blockIdx.x & 31;

    // stage Q (once)
    {
        const uint4* Qg = g_Q4 + (size_t)(b * 32 + qt) * 4096;
        for (int i = tid; i < 4096; i += 256) sts128(QS + i * 16, Qg[i]);
    }

    float Oacc[2][16][4];
#pragma unroll
    for (int mt = 0; mt < 2; mt++)
#pragma unroll
        for (int ft = 0; ft < 16; ft++)
#pragma unroll
            for (int c = 0; c < 4; c++) Oacc[mt][ft][c] = 0.f;
    float denA[2] = {0.f, 0.f}, denB[2] = {0.f, 0.f};

    const uint4* Kg = g_K4 + (size_t)b * 8 * 4096;
    const uint4* Vg = g_V4 + (size_t)b * 8 * 4096;

    for (int kt = 0; kt < 8; kt++) {
        __syncthreads();                       // prev GEMM2 done with VS/PS (and Q staged)
        {
            const uint4* K0 = Kg + (size_t)kt * 4096;
            const uint4* V0 = Vg + (size_t)kt * 4096;
            for (int i = tid; i < 4096; i += 256) {
                sts128(KS + i * 16, K0[i]);
                sts128(VS + i * 16, V0[i]);
            }
        }
        __syncthreads();

        // ---- GEMM1 + softmax + P store, two 32-key halves ----
#pragma unroll
        for (int nh = 0; nh < 2; nh++) {
            float S[2][4][4];
#pragma unroll
            for (int mt = 0; mt < 2; mt++)
#pragma unroll
                for (int j = 0; j < 4; j++)
#pragma unroll
                    for (int c = 0; c < 4; c++) S[mt][j][c] = 0.f;

#pragma unroll
            for (int ks = 0; ks < 16; ks++) {
                const uint32_t fch = (uint32_t)(ks >> 2) * 16384u;
                uint32_t afr[2][4];
                const int fA = 16 * ks + ((lane & 16) >> 1);
#pragma unroll
                for (int mt = 0; mt < 2; mt++) {
                    int row = 32 * wm + 16 * mt + (lane & 15);
                    ldsm4(afr[mt], QS + fch + sw128((uint32_t)row * 128u + (uint32_t)(fA & 63) * 2u));
                }
                const int fB = 16 * ks + (lane & 8);
                uint32_t bfr[2][4];
#pragma unroll
                for (int xx = 0; xx < 2; xx++) {
                    int key = 64 * wn + 32 * nh + 16 * xx + (lane & 7) + ((lane & 16) >> 1);
                    ldsm4(bfr[xx], KS + fch + sw128((uint32_t)key * 128u + (uint32_t)(fB & 63) * 2u));
                }
#pragma unroll
                for (int mt = 0; mt < 2; mt++) {
                    mma16816(S[mt][0], afr[mt], bfr[0][0], bfr[0][1]);
                    mma16816(S[mt][1], afr[mt], bfr[0][2], bfr[0][3]);
                    mma16816(S[mt][2], afr[mt], bfr[1][0], bfr[1][1]);
                    mma16816(S[mt][3], afr[mt], bfr[1][2], bfr[1][3]);
                }
            }
            // softmax (|s|<=1: no max needed) + pack to f16 + store P
#pragma unroll
            for (int mt = 0; mt < 2; mt++) {
                const int q0 = 32 * wm + 16 * mt + (lane >> 2);
                const int q1 = q0 + 8;
#pragma unroll
                for (int j = 0; j < 4; j++) {
                    float e0 = __expf(S[mt][j][0]), e1 = __expf(S[mt][j][1]);
                    float e2 = __expf(S[mt][j][2]), e3 = __expf(S[mt][j][3]);
                    denA[mt] += e0 + e1; denB[mt] += e2 + e3;
                    __half2 h01 = __floats2half2_rn(e0, e1);
                    __half2 h23 = __floats2half2_rn(e2, e3);
                    const uint32_t kb = (uint32_t)(128 * wn + 64 * nh + 16 * j + 4 * (lane & 3));
                    const uint32_t ch = kb >> 4, off = kb & 15;
                    sts32(PS + (uint32_t)q0 * 256u + ((ch ^ (uint32_t)(q0 & 7)) << 4) + off,
                          *(uint32_t*)&h01);
                    sts32(PS + (uint32_t)q1 * 256u + ((ch ^ (uint32_t)(q1 & 7)) << 4) + off,
                          *(uint32_t*)&h23);
                }
            }
        }
        __syncthreads();                       // P visible; KS reads done

        // ---- GEMM2: O += P(128x128) * V(128x256) ----
#pragma unroll
        for (int ks = 0; ks < 8; ks++) {
            uint32_t ap[2][4];
            const uint32_t kbyte = 32u * ks + (uint32_t)(lane & 16);
            const uint32_t ch = kbyte >> 4;
#pragma unroll
            for (int mt = 0; mt < 2; mt++) {
                int q = 32 * wm + 16 * mt + (lane & 15);
                ldsm4(ap[mt], PS + (uint32_t)q * 256u + ((ch ^ (uint32_t)(q & 7)) << 4));
            }
            const int keyc = 16 * ks + (lane & 8);
            const uint32_t vch = (uint32_t)(ks >> 2) * 32768u;
#pragma unroll
            for (int xx = 0; xx < 8; xx++) {
                int f = 128 * wn + 16 * xx + (lane & 7) + ((lane & 16) >> 1);
                uint32_t bv[4];
                ldsm4(bv, VS + vch + sw128((uint32_t)f * 128u + (uint32_t)(keyc & 63) * 2u));
                mma16816(Oacc[0][2 * xx],     ap[0], bv[0], bv[1]);
                mma16816(Oacc[0][2 * xx + 1], ap[0], bv[2], bv[3]);
                mma16816(Oacc[1][2 * xx],     ap[1], bv[0], bv[1]);
                mma16816(Oacc[1][2 * xx + 1], ap[1], bv[2], bv[3]);
            }
        }
    }

    // den: reduce over the 4 lanes of a row group, publish per wn-half, combine
#pragma unroll
    for (int mt = 0; mt < 2; mt++) {
        float dA = denA[mt], dB = denB[mt];
        dA += __shfl_xor_sync(0xffffffffu, dA, 1); dA += __shfl_xor_sync(0xffffffffu, dA, 2);
        dB += __shfl_xor_sync(0xffffffffu, dB, 1); dB += __shfl_xor_sync(0xffffffffu, dB, 2);
        if ((lane & 3) == 0) {
            int q = 32 * wm + 16 * mt + (lane >> 2);
            sts32(DS + (uint32_t)(wn * 128 + q) * 4u,     __float_as_uint(dA));
            sts32(DS + (uint32_t)(wn * 128 + q + 8) * 4u, __float_as_uint(dB));
        }
    }
    __syncthreads();

    // epilogue: divide + scatter to out[(b*256+f)*4096 + q]
#pragma unroll
    for (int mt = 0; mt < 2; mt++) {
        const int q0 = 32 * wm + 16 * mt + (lane >> 2), q1 = q0 + 8;
        const float inv0 = 1.0f / (denp[q0] + denp[128 + q0]);
        const float inv1 = 1.0f / (denp[q1] + denp[128 + q1]);
        const size_t g0 = (size_t)qt * 128 + q0, g1 = (size_t)qt * 128 + q1;
#pragma unroll
        for (int ft = 0; ft < 16; ft++) {
            const int f = 128 * wn + 8 * ft + 2 * (lane & 3);
            float* o0 = out + ((size_t)b * 256 + f) * 4096;
            o0[g0]          = Oacc[mt][ft][0] * inv0;
            (o0 + 4096)[g0] = Oacc[mt][ft][1] * inv0;
            o0[g1]          = Oacc[mt][ft][2] * inv1;
            (o0 + 4096)[g1] = Oacc[mt][ft][3] * inv1;
        }
    }
}

// ---------------------------------------------------------------------------
extern "C" void kernel_launch(void* const* d_in, const int* in_sizes, int n_in,
                              void* d_out, int out_size)
{
    const float* x   = (const float*)d_in[0];
    const float* wq  = (const float*)d_in[1];
    const float* wkv = (const float*)d_in[2];
    float* out = (float*)d_out;

    cudaFuncSetAttribute(attn_kernel,
                         cudaFuncAttributeMaxDynamicSharedMemorySize, SDYN_BYTES);

    qproj_kernel <<<B_ * 128, 256>>>(x, wq);
    kvproj_kernel<<<B_ * 32,  256>>>(x, wkv);
    attn_kernel  <<<B_ * 32,  256, SDYN_BYTES>>>(out);
}

// round 11
// speedup vs baseline: 1.2157x; 1.2157x over previous
#include <cuda_runtime.h>
#include <cuda_fp16.h>
#include <math.h>
#include <cstdint>

#define B_   8

// ---------------------------------------------------------------------------
// Global scratch (fp16, SW128-swizzled chunk blobs; blob layout == smem image)
// Q: per (b, qtile<32>): 4 chunks x 16KB ([128 rows][64 f], 128B rows, SW128)
// K: per (b, ktile<8>):  4 chunks x 16KB ([128 keys][64 f])
// V: per (b, ktile<8>):  2 chunks x 32KB ([256 f][64 keys]  (Vt))
// ---------------------------------------------------------------------------
__device__ uint4 g_Q4[(size_t)B_ * 32 * 4096];   // 16 MB
__device__ uint4 g_K4[(size_t)B_ * 8 * 4096];    //  4 MB
__device__ uint4 g_V4[(size_t)B_ * 8 * 4096];    //  4 MB

__device__ __forceinline__ uint32_t sw128(uint32_t o) { return o ^ ((o >> 3) & 0x70); }

__device__ __forceinline__ uint32_t smem_u32(const void* p) {
    uint32_t a;
    asm("{ .reg .u64 t; cvta.to.shared.u64 t, %1; cvt.u32.u64 %0, t; }" : "=r"(a) : "l"(p));
    return a;
}
__device__ __forceinline__ void ldsm4(uint32_t* r, uint32_t a) {
    asm volatile("ldmatrix.sync.aligned.m8n8.x4.shared.b16 {%0,%1,%2,%3}, [%4];"
                 : "=r"(r[0]), "=r"(r[1]), "=r"(r[2]), "=r"(r[3]) : "r"(a));
}
__device__ __forceinline__ void mma16816(float* d, const uint32_t* a, uint32_t b0, uint32_t b1) {
    asm volatile("mma.sync.aligned.m16n8k16.row.col.f32.f16.f16.f32 "
                 "{%0,%1,%2,%3}, {%4,%5,%6,%7}, {%8,%9}, {%0,%1,%2,%3};"
                 : "+f"(d[0]), "+f"(d[1]), "+f"(d[2]), "+f"(d[3])
                 : "r"(a[0]), "r"(a[1]), "r"(a[2]), "r"(a[3]), "r"(b0), "r"(b1));
}
__device__ __forceinline__ void sts128(uint32_t a, uint4 v) {
    asm volatile("st.shared.v4.b32 [%0], {%1,%2,%3,%4};"
                 :: "r"(a), "r"(v.x), "r"(v.y), "r"(v.z), "r"(v.w) : "memory");
}
__device__ __forceinline__ void sts32(uint32_t a, uint32_t v) {
    asm volatile("st.shared.b32 [%0], %1;" :: "r"(a), "r"(v) : "memory");
}
__device__ __forceinline__ void cpa16(uint32_t dst, const void* src) {
    asm volatile("cp.async.cg.shared.global [%0], [%1], 16;" :: "r"(dst), "l"(src) : "memory");
}
#define CP_COMMIT() asm volatile("cp.async.commit_group;" ::: "memory")
#define CP_WAIT(n)  asm volatile("cp.async.wait_group %0;" :: "n"(n) : "memory")

// ---------------------------------------------------------------------------
// Kernel 1: Q projection + L2 norm -> swizzled fp16 chunk blobs.
// Block: 256 thr = 8 warps (warp = n); each thread handles 2 hw (float2).
// ---------------------------------------------------------------------------
__global__ void __launch_bounds__(256) qproj_kernel(const float* __restrict__ x,
                                                    const float* __restrict__ wq)
{
    __shared__ float s_w[64 * 32];        // [c][d]
    __shared__ float s_ss[8][64];
    __shared__ uint4 s_q[64 * 32];        // 64 rows x 32 16B-chunks (xor-swizzled)
    const int t = threadIdx.x;
    for (int i = t; i < 2048; i += 256) { int d = i >> 6, c = i & 63; s_w[c * 32 + d] = wq[i]; }
    __syncthreads();

    const int b = blockIdx.x >> 6, tile = blockIdx.x & 63;   // 64 hw per tile
    const int n = t >> 5, r = t & 31;
    const float* xp = x + (size_t)b * 64 * 8 * 4096 + (size_t)n * 4096 + tile * 64 + 2 * r;

    float acc0[32], acc1[32];
#pragma unroll
    for (int d = 0; d < 32; d++) { acc0[d] = 0.f; acc1[d] = 0.f; }
#pragma unroll 4
    for (int c = 0; c < 64; c++) {
        float2 xv = *(const float2*)&xp[(size_t)c * 32768];
#pragma unroll
        for (int m = 0; m < 8; m++) {
            float4 w4 = *(const float4*)&s_w[c * 32 + 4 * m];
            acc0[4*m+0] += xv.x * w4.x; acc0[4*m+1] += xv.x * w4.y;
            acc0[4*m+2] += xv.x * w4.z; acc0[4*m+3] += xv.x * w4.w;
            acc1[4*m+0] += xv.y * w4.x; acc1[4*m+1] += xv.y * w4.y;
            acc1[4*m+2] += xv.y * w4.z; acc1[4*m+3] += xv.y * w4.w;
        }
    }
    float ss0 = 0.f, ss1 = 0.f;
#pragma unroll
    for (int d = 0; d < 32; d++) { ss0 += acc0[d] * acc0[d]; ss1 += acc1[d] * acc1[d]; }
    s_ss[n][2 * r] = ss0; s_ss[n][2 * r + 1] = ss1;
    __syncthreads();
    float t0 = 0.f, t1 = 0.f;
#pragma unroll
    for (int w = 0; w < 8; w++) { t0 += s_ss[w][2 * r]; t1 += s_ss[w][2 * r + 1]; }
    const float inv0 = 1.0f / fmaxf(sqrtf(t0), 1e-12f);
    const float inv1 = 1.0f / fmaxf(sqrtf(t1), 1e-12f);

    __half* sq = (__half*)s_q;
    const int r0 = 2 * r, r1 = 2 * r + 1;
#pragma unroll
    for (int d = 0; d < 32; d++) {
        sq[r0 * 256 + ((d ^ (r0 & 31)) << 3) + n] = __float2half_rn(acc0[d] * inv0);
        sq[r1 * 256 + ((d ^ (r1 & 31)) << 3) + n] = __float2half_rn(acc1[d] * inv1);
    }
    __syncthreads();

    const int qt = tile >> 1, rbase = (tile & 1) * 64;
    uint4* dst = g_Q4 + (size_t)(b * 32 + qt) * 4096;
    for (int i = t; i < 2048; i += 256) {
        int rr = i >> 5, j = i & 31;
        uint4 v = s_q[rr * 32 + (j ^ (rr & 31))];
        uint32_t off = sw128((uint32_t)(rbase + rr) * 128 + (j & 7) * 16);
        *(uint4*)((char*)(dst + (j >> 3) * 1024) + off) = v;
    }
}

// ---------------------------------------------------------------------------
// Kernel 2: KV projection (2x-subsampled grid) + K norm -> blobs.
// ---------------------------------------------------------------------------
__global__ void __launch_bounds__(256) kvproj_kernel(const float* __restrict__ x,
                                                     const float* __restrict__ wkv)
{
    __shared__ float s_w[64 * 64];        // [c][e]
    __shared__ float s_ss[8][32];
    __shared__ uint4 s_buf[1024];         // 16KB, reused K then V
    const int t = threadIdx.x;
    for (int i = t; i < 4096; i += 256) { int e = i >> 6, c = i & 63; s_w[c * 64 + e] = wkv[i]; }
    __syncthreads();

    const int b = blockIdx.x >> 5, h2 = blockIdx.x & 31;
    const int n = t >> 5, w2 = t & 31;
    const float* xp = x + (size_t)b * 64 * 8 * 4096 + (size_t)n * 4096 + (2 * h2) * 64 + 2 * w2;

    float acc[64];
#pragma unroll
    for (int e = 0; e < 64; e++) acc[e] = 0.f;
#pragma unroll 4
    for (int c = 0; c < 64; c++) {
        float xv = xp[(size_t)c * 32768];
#pragma unroll
        for (int m = 0; m < 16; m++) {
            float4 w4 = *(const float4*)&s_w[c * 64 + 4 * m];
            acc[4*m+0] += xv * w4.x; acc[4*m+1] += xv * w4.y;
            acc[4*m+2] += xv * w4.z; acc[4*m+3] += xv * w4.w;
        }
    }
    float ss = 0.f;
#pragma unroll
    for (int d = 0; d < 32; d++) ss += acc[d] * acc[d];
    s_ss[n][w2] = ss;
    __syncthreads();
    float tot = 0.f;
#pragma unroll
    for (int w = 0; w < 8; w++) tot += s_ss[w][w2];
    const float inv = 1.0f / fmaxf(sqrtf(tot), 1e-12f);

    // --- K stage + write ---
    __half* sk = (__half*)s_buf;
#pragma unroll
    for (int d = 0; d < 32; d++)
        sk[w2 * 256 + ((d ^ w2) << 3) + n] = __float2half_rn(acc[d] * inv);
    __syncthreads();
    const int kt = h2 >> 2, rbase = (h2 & 3) * 32;
    uint4* kd = g_K4 + (size_t)(b * 8 + kt) * 4096;
    for (int i = t; i < 1024; i += 256) {
        int rr = i >> 5, j = i & 31;
        uint4 v = s_buf[rr * 32 + (j ^ rr)];
        uint32_t off = sw128((uint32_t)(rbase + rr) * 128 + (j & 7) * 16);
        *(uint4*)((char*)(kd + (j >> 3) * 1024) + off) = v;
    }
    __syncthreads();

    // --- Vt stage ([f][32 keys]) + write ---
    __half* sv = (__half*)s_buf;
#pragma unroll
    for (int d = 0; d < 32; d++)
        sv[(d * 8 + n) * 32 + w2] = __float2half_rn(acc[32 + d]);
    __syncthreads();
    const int kc = (h2 & 3) >> 1, colbase = (h2 & 1) * 32;
    uint4* vd = g_V4 + ((size_t)(b * 8 + kt) * 2 + kc) * 2048;
    for (int i = t; i < 1024; i += 256) {
        int f = i >> 2, k8 = i & 3;
        uint4 v = s_buf[i];
        uint32_t off = sw128((uint32_t)f * 128 + colbase * 2 + k8 * 16);
        *(uint4*)((char*)vd + off) = v;
    }
}

// ---------------------------------------------------------------------------
// Kernel 3: HMMA attention, 512 threads = 16 warps in 4(M) x 4(N),
// cp.async pipelined staging (V_kt overlaps GEMM1, K_{kt+1} overlaps GEMM2).
// Smem: Q 64K | K 64K | Vt 64K | P 32K | den 2K = 226K (+align).
// ---------------------------------------------------------------------------
#define SDYN_BYTES 232448

__global__ void __launch_bounds__(512, 1) attn_kernel(float* __restrict__ out)
{
    extern __shared__ unsigned char smraw[];
    const uint32_t sbase = (smem_u32(smraw) + 1023) & ~1023u;
    const uint32_t QS = sbase, KS = sbase + 65536, VS = sbase + 131072;
    const uint32_t PS = sbase + 196608, DS = sbase + 229376;
    float* denp = (float*)(smraw + (size_t)(DS - smem_u32(smraw)));

    const int tid = threadIdx.x, lane = tid & 31, w = tid >> 5;
    const int wm = w & 3, wn = w >> 2;                 // 4 x 4 warp grid
    const int b = blockIdx.x >> 5, qt = blockIdx.x & 31;

    const uint4* Qg = g_Q4 + (size_t)(b * 32 + qt) * 4096;
    const uint4* Kg = g_K4 + (size_t)b * 8 * 4096;
    const uint4* Vg = g_V4 + (size_t)b * 8 * 4096;

    // prologue: async-stage Q and K0 as one group
    for (int i = tid; i < 4096; i += 512) cpa16(QS + i * 16, Qg + i);
    for (int i = tid; i < 4096; i += 512) cpa16(KS + i * 16, Kg + i);
    CP_COMMIT();

    float Oacc[2][8][4];
#pragma unroll
    for (int mt = 0; mt < 2; mt++)
#pragma unroll
        for (int ft = 0; ft < 8; ft++)
#pragma unroll
            for (int c = 0; c < 4; c++) Oacc[mt][ft][c] = 0.f;
    float denA[2] = {0.f, 0.f}, denB[2] = {0.f, 0.f};

    for (int kt = 0; kt < 8; kt++) {
        __syncthreads();                 // prior GEMM2 done reading VS/PS
        // stage V_kt (overlaps GEMM1)
        for (int i = tid; i < 4096; i += 512) cpa16(VS + i * 16, Vg + kt * 4096 + i);
        CP_COMMIT();
        CP_WAIT(1);                      // K_kt (and Q) complete
        __syncthreads();

        // ---- GEMM1: S(32q x 32keys per warp), K = 256 ----
        float S[2][4][4];
#pragma unroll
        for (int mt = 0; mt < 2; mt++)
#pragma unroll
            for (int j = 0; j < 4; j++)
#pragma unroll
                for (int c = 0; c < 4; c++) S[mt][j][c] = 0.f;

#pragma unroll
        for (int ks = 0; ks < 16; ks++) {
            const uint32_t fch = (uint32_t)(ks >> 2) * 16384u;
            const int fA = 16 * ks + ((lane & 16) >> 1);
            uint32_t afr[2][4];
#pragma unroll
            for (int mt = 0; mt < 2; mt++) {
                int row = 32 * wm + 16 * mt + (lane & 15);
                ldsm4(afr[mt], QS + fch + sw128((uint32_t)row * 128u + (uint32_t)(fA & 63) * 2u));
            }
            const int fB = 16 * ks + (lane & 8);
            uint32_t bfr[2][4];
#pragma unroll
            for (int xx = 0; xx < 2; xx++) {
                int key = 32 * wn + 16 * xx + (lane & 7) + ((lane & 16) >> 1);
                ldsm4(bfr[xx], KS + fch + sw128((uint32_t)key * 128u + (uint32_t)(fB & 63) * 2u));
            }
#pragma unroll
            for (int mt = 0; mt < 2; mt++) {
                mma16816(S[mt][0], afr[mt], bfr[0][0], bfr[0][1]);
                mma16816(S[mt][1], afr[mt], bfr[0][2], bfr[0][3]);
                mma16816(S[mt][2], afr[mt], bfr[1][0], bfr[1][1]);
                mma16816(S[mt][3], afr[mt], bfr[1][2], bfr[1][3]);
            }
        }

        // ---- softmax (|s|<=1: no max bookkeeping) + pack P to f16 ----
#pragma unroll
        for (int mt = 0; mt < 2; mt++) {
            const int q0 = 32 * wm + 16 * mt + (lane >> 2);
            const int q1 = q0 + 8;
#pragma unroll
            for (int j = 0; j < 4; j++) {
                float e0 = __expf(S[mt][j][0]), e1 = __expf(S[mt][j][1]);
                float e2 = __expf(S[mt][j][2]), e3 = __expf(S[mt][j][3]);
                denA[mt] += e0 + e1; denB[mt] += e2 + e3;
                __half2 h01 = __floats2half2_rn(e0, e1);
                __half2 h23 = __floats2half2_rn(e2, e3);
                const uint32_t kb = (uint32_t)(64 * wn + 16 * j + 4 * (lane & 3));
                const uint32_t ch = kb >> 4, off = kb & 15;
                sts32(PS + (uint32_t)q0 * 256u + ((ch ^ (uint32_t)(q0 & 7)) << 4) + off,
                      *(uint32_t*)&h01);
                sts32(PS + (uint32_t)q1 * 256u + ((ch ^ (uint32_t)(q1 & 7)) << 4) + off,
                      *(uint32_t*)&h23);
            }
        }
        CP_WAIT(0);                      // V_kt complete
        __syncthreads();                 // P visible; all warps past GEMM1 (KS free)
        if (kt < 7) {                    // stage K_{kt+1} (overlaps GEMM2)
            for (int i = tid; i < 4096; i += 512) cpa16(KS + i * 16, Kg + (kt + 1) * 4096 + i);
            CP_COMMIT();
        }

        // ---- GEMM2: O(32q x 64f per warp) += P * V ----
#pragma unroll
        for (int ks = 0; ks < 8; ks++) {
            uint32_t ap[2][4];
            const uint32_t kbyte = 32u * ks + (uint32_t)(lane & 16);
            const uint32_t ch = kbyte >> 4;
#pragma unroll
            for (int mt = 0; mt < 2; mt++) {
                int q = 32 * wm + 16 * mt + (lane & 15);
                ldsm4(ap[mt], PS + (uint32_t)q * 256u + ((ch ^ (uint32_t)(q & 7)) << 4));
            }
            const int keyc = 16 * ks + (lane & 8);
            const uint32_t vch = (uint32_t)(ks >> 2) * 32768u;
#pragma unroll
            for (int xx = 0; xx < 4; xx++) {
                int f = 64 * wn + 16 * xx + (lane & 7) + ((lane & 16) >> 1);
                uint32_t bv[4];
                ldsm4(bv, VS + vch + sw128((uint32_t)f * 128u + (uint32_t)(keyc & 63) * 2u));
                mma16816(Oacc[0][2 * xx],     ap[0], bv[0], bv[1]);
                mma16816(Oacc[0][2 * xx + 1], ap[0], bv[2], bv[3]);
                mma16816(Oacc[1][2 * xx],     ap[1], bv[0], bv[1]);
                mma16816(Oacc[1][2 * xx + 1], ap[1], bv[2], bv[3]);
            }
        }
    }

    // den: quad-reduce, publish per wn strip, combine 4 strips
#pragma unroll
    for (int mt = 0; mt < 2; mt++) {
        float dA = denA[mt], dB = denB[mt];
        dA += __shfl_xor_sync(0xffffffffu, dA, 1); dA += __shfl_xor_sync(0xffffffffu, dA, 2);
        dB += __shfl_xor_sync(0xffffffffu, dB, 1); dB += __shfl_xor_sync(0xffffffffu, dB, 2);
        if ((lane & 3) == 0) {
            int q = 32 * wm + 16 * mt + (lane >> 2);
            sts32(DS + (uint32_t)(wn * 128 + q) * 4u,     __float_as_uint(dA));
            sts32(DS + (uint32_t)(wn * 128 + q + 8) * 4u, __float_as_uint(dB));
        }
    }
    __syncthreads();

    // epilogue: divide + scatter to out[(b*256+f)*4096 + q]
#pragma unroll
    for (int mt = 0; mt < 2; mt++) {
        const int q0 = 32 * wm + 16 * mt + (lane >> 2), q1 = q0 + 8;
        const float inv0 = 1.0f / (denp[q0] + denp[128 + q0] + denp[256 + q0] + denp[384 + q0]);
        const float inv1 = 1.0f / (denp[q1] + denp[128 + q1] + denp[256 + q1] + denp[384 + q1]);
        const size_t g0 = (size_t)qt * 128 + q0, g1 = (size_t)qt * 128 + q1;
#pragma unroll
        for (int ft = 0; ft < 8; ft++) {
            const int f = 64 * wn + 8 * ft + 2 * (lane & 3);
            float* o0 = out + ((size_t)b * 256 + f) * 4096;
            o0[g0]          = Oacc[mt][ft][0] * inv0;
            (o0 + 4096)[g0] = Oacc[mt][ft][1] * inv0;
            o0[g1]          = Oacc[mt][ft][2] * inv1;
            (o0 + 4096)[g1] = Oacc[mt][ft][3] * inv1;
        }
    }
}

// ---------------------------------------------------------------------------
extern "C" void kernel_launch(void* const* d_in, const int* in_sizes, int n_in,
                              void* d_out, int out_size)
{
    const float* x   = (const float*)d_in[0];
    const float* wq  = (const float*)d_in[1];
    const float* wkv = (const float*)d_in[2];
    float* out = (float*)d_out;

    cudaFuncSetAttribute(attn_kernel,
                         cudaFuncAttributeMaxDynamicSharedMemorySize, SDYN_BYTES);

    qproj_kernel <<<B_ * 64, 256>>>(x, wq);
    kvproj_kernel<<<B_ * 32, 256>>>(x, wkv);
    attn_kernel  <<<B_ * 32, 512, SDYN_BYTES>>>(out);
}